// round 15
// baseline (speedup 1.0000x reference)
#include <cuda_runtime.h>
#include <math.h>

// ---------------- problem constants ----------------
// B=32, HID=128, RES=64, K=D=64
// out layout: [0]=loss, [1..2097152]=x_re, [2097153]=perplexity, [2097154..]=qn
#define OFF_XRE   1
#define OFF_PERP  2097153
#define OFF_QN    2097154

// ---------------- scratch (device globals; no allocation) ----------------
__device__ float g_big[33554432];   // 32*64*128*128 : enc_c1 out, dec_c2 out
__device__ float g_x  [16777216];   // 32*128*64*64  : enc_c2 out
__device__ float g_y  [16777216];   // 32*128*64*64  : res-block state (enc & dec)
__device__ float g_h  [ 8388608];   // 32*64*64*64   : res intermediate
__device__ float g_z  [ 8388608];   // z NHWC rows; reused as ALIGNED qn copy after VQ
__device__ int   g_idx[131072];
__device__ float g_w1t[128*64*9];   // transformed dec_c1 weights (OIHW conv form)
__device__ float g_ssep[2048];
__device__ int   g_cnt[64];

// ---------------- packed f32x2 helpers ----------------
using u64 = unsigned long long;

__device__ __forceinline__ u64 pk(float a, float b) {
    u64 r; asm("mov.b64 %0,{%1,%2};" : "=l"(r) : "f"(a), "f"(b)); return r;
}
__device__ __forceinline__ u64 pk1(float a) {
    u64 r; asm("mov.b64 %0,{%1,%1};" : "=l"(r) : "f"(a)); return r;
}
__device__ __forceinline__ void upk(u64 v, float& a, float& b) {
    asm("mov.b64 {%0,%1},%2;" : "=f"(a), "=f"(b) : "l"(v));
}
__device__ __forceinline__ void fma2(u64& d, u64 a, u64 b) {
    asm("fma.rn.f32x2 %0,%1,%2,%0;" : "+l"(d) : "l"(a), "l"(b));
}
__device__ __forceinline__ float4 relu4(float4 v) {
    v.x = fmaxf(v.x, 0.f); v.y = fmaxf(v.y, 0.f);
    v.z = fmaxf(v.z, 0.f); v.w = fmaxf(v.w, 0.f);
    return v;
}

// store acc[4px][4copair] to channel-major planes
__device__ __forceinline__ void store4x8(u64 acc[4][4], float* op, int plane, bool relu) {
    #pragma unroll
    for (int cp = 0; cp < 4; cp++) {
        float4 o0, o1;
        upk(acc[0][cp], o0.x, o1.x);
        upk(acc[1][cp], o0.y, o1.y);
        upk(acc[2][cp], o0.z, o1.z);
        upk(acc[3][cp], o0.w, o1.w);
        if (relu) { o0 = relu4(o0); o1 = relu4(o1); }
        *reinterpret_cast<float4*>(op + (size_t)(2*cp)   * plane) = o0;
        *reinterpret_cast<float4*>(op + (size_t)(2*cp+1) * plane) = o1;
    }
}

// ---------------- conv k=4 s=2 p=1, 8 co x 4 px per thread ----------------
template<int CIN, int COUT, int HIN, bool RELU_OUT>
__global__ void __launch_bounds__(256, 3)
conv_k4s2(const float* __restrict__ in, const float* __restrict__ w,
          const float* __restrict__ bias, float* __restrict__ out)
{
    constexpr int HOUT = HIN / 2;
    __shared__ __align__(16) float ws[CIN * 128];
    const int tid = threadIdx.x;
    const int cog = blockIdx.y;
    const int b   = blockIdx.z;
    for (int e = tid; e < CIN * 128; e += 256) {
        int u = e & 7; int rest = e >> 3; int tap = rest & 15; int ci = rest >> 4;
        ws[e] = w[((size_t)(cog * 8 + u) * CIN + ci) * 16 + tap];
    }
    __syncthreads();
    const int t   = blockIdx.x * 256 + tid;
    const int p4  = t * 4;
    const int oh  = p4 / HOUT;
    const int ow4 = p4 % HOUT;
    u64 acc[4][4];
    #pragma unroll
    for (int cp = 0; cp < 4; cp++) {
        u64 bp = pk(bias[cog*8 + 2*cp], bias[cog*8 + 2*cp + 1]);
        #pragma unroll
        for (int px = 0; px < 4; px++) acc[px][cp] = bp;
    }
    const float* inb = in + (size_t)b * CIN * HIN * HIN;
    for (int ci = 0; ci < CIN; ci++) {
        const float* inc = inb + (size_t)ci * HIN * HIN;
        const float* wc  = ws + ci * 128;
        #pragma unroll
        for (int kh = 0; kh < 4; kh++) {
            int ih = oh * 2 + kh - 1;
            if ((unsigned)ih >= (unsigned)HIN) continue;
            const float* rp = inc + ih * HIN + ow4 * 2;
            float vl = (ow4 > 0) ? rp[-1] : 0.f;
            float4 c0 = *reinterpret_cast<const float4*>(rp);
            float4 c1 = *reinterpret_cast<const float4*>(rp + 4);
            float vr = (ow4 < HOUT - 4) ? rp[8] : 0.f;
            u64 v[10] = { pk1(vl), pk1(c0.x), pk1(c0.y), pk1(c0.z), pk1(c0.w),
                          pk1(c1.x), pk1(c1.y), pk1(c1.z), pk1(c1.w), pk1(vr) };
            #pragma unroll
            for (int kw = 0; kw < 4; kw++) {
                ulonglong2 w01 = *reinterpret_cast<const ulonglong2*>(wc + (kh*4+kw)*8);
                ulonglong2 w23 = *reinterpret_cast<const ulonglong2*>(wc + (kh*4+kw)*8 + 4);
                #pragma unroll
                for (int px = 0; px < 4; px++) {
                    u64 xv = v[2*px + kw];
                    fma2(acc[px][0], w01.x, xv);
                    fma2(acc[px][1], w01.y, xv);
                    fma2(acc[px][2], w23.x, xv);
                    fma2(acc[px][3], w23.y, xv);
                }
            }
        }
    }
    float* op = out + ((size_t)b * COUT + cog * 8) * (HOUT * HOUT) + p4;
    store4x8(acc, op, HOUT * HOUT, RELU_OUT);
}

// ---------------- conv 3x3 s=1 p=1 at 64x64, 8 co x 4 px per thread ----------------
// (256,3): 84-reg cap gives ptxas room to software-pipeline the unroll-2 ci loop
template<int CIN, int COUT, bool RELU_IN, bool RELU_OUT, bool BIAS>
__global__ void __launch_bounds__(256, 3)
conv3x3_k(const float* __restrict__ in, const float* __restrict__ w,
          const float* __restrict__ bias, float* __restrict__ out)
{
    __shared__ __align__(16) float ws[CIN * 72];
    const int tid = threadIdx.x;
    const int cog = blockIdx.y;
    const int b   = blockIdx.z;
    for (int e = tid; e < CIN * 72; e += 256) {
        int u = e & 7; int rest = e >> 3; int tap = rest % 9; int ci = rest / 9;
        ws[e] = w[((size_t)(cog * 8 + u) * CIN + ci) * 9 + tap];
    }
    __syncthreads();
    const int t   = blockIdx.x * 256 + tid;   // 0..1023
    const int oh  = t >> 4;
    const int ow4 = (t & 15) << 2;
    u64 acc[4][4];
    #pragma unroll
    for (int cp = 0; cp < 4; cp++) {
        u64 bp = BIAS ? pk(bias[cog*8 + 2*cp], bias[cog*8 + 2*cp + 1]) : 0ull;
        #pragma unroll
        for (int px = 0; px < 4; px++) acc[px][cp] = bp;
    }
    const float* inb = in + (size_t)b * CIN * 4096;
    #pragma unroll 2
    for (int ci = 0; ci < CIN; ci++) {
        const float* inc = inb + ci * 4096;
        const float* wc  = ws + ci * 72;
        #pragma unroll
        for (int kh = 0; kh < 3; kh++) {
            int ih = oh + kh - 1;
            if ((unsigned)ih >= 64u) continue;
            const float* rp = inc + ih * 64 + ow4;
            float vl = (ow4 > 0)  ? rp[-1] : 0.f;
            float4 c  = *reinterpret_cast<const float4*>(rp);
            float vr = (ow4 < 60) ? rp[4]  : 0.f;
            if (RELU_IN) {
                vl = fmaxf(vl, 0.f); vr = fmaxf(vr, 0.f); c = relu4(c);
            }
            u64 v[6] = { pk1(vl), pk1(c.x), pk1(c.y), pk1(c.z), pk1(c.w), pk1(vr) };
            #pragma unroll
            for (int kw = 0; kw < 3; kw++) {
                ulonglong2 w01 = *reinterpret_cast<const ulonglong2*>(wc + (kh*3+kw)*8);
                ulonglong2 w23 = *reinterpret_cast<const ulonglong2*>(wc + (kh*3+kw)*8 + 4);
                #pragma unroll
                for (int px = 0; px < 4; px++) {
                    u64 xv = v[px + kw];
                    fma2(acc[px][0], w01.x, xv);
                    fma2(acc[px][1], w01.y, xv);
                    fma2(acc[px][2], w23.x, xv);
                    fma2(acc[px][3], w23.y, xv);
                }
            }
        }
    }
    float* op = out + ((size_t)b * COUT + cog * 8) * 4096 + (oh * 64 + ow4);
    store4x8(acc, op, 4096, RELU_OUT);
}

// ---------------- residual add: x = relu(x) + W2(128x64) @ h ----------------
__global__ void __launch_bounds__(256, 4)
res_add_k(float* __restrict__ x, const float* __restrict__ h,
          const float* __restrict__ w2)
{
    __shared__ __align__(16) float ws[64 * 8];
    const int tid = threadIdx.x;
    const int cog = blockIdx.y;   // 16 groups of 8 (COUT=128)
    const int b   = blockIdx.z;
    for (int e = tid; e < 512; e += 256) {
        int u = e & 7; int ci = e >> 3;
        ws[e] = w2[(cog * 8 + u) * 64 + ci];
    }
    __syncthreads();
    const int p4 = (blockIdx.x * 256 + tid) * 4;
    float* xp = x + ((size_t)b * 128 + cog * 8) * 4096 + p4;
    u64 acc[4][4];
    #pragma unroll
    for (int cp = 0; cp < 4; cp++) {
        float4 a = relu4(*reinterpret_cast<const float4*>(xp + (size_t)(2*cp)   * 4096));
        float4 c = relu4(*reinterpret_cast<const float4*>(xp + (size_t)(2*cp+1) * 4096));
        acc[0][cp] = pk(a.x, c.x); acc[1][cp] = pk(a.y, c.y);
        acc[2][cp] = pk(a.z, c.z); acc[3][cp] = pk(a.w, c.w);
    }
    const float* hb = h + (size_t)b * 64 * 4096 + p4;
    #pragma unroll 2
    for (int ci = 0; ci < 64; ci++) {
        float4 hv = *reinterpret_cast<const float4*>(hb + (size_t)ci * 4096);
        u64 h0 = pk1(hv.x), h1 = pk1(hv.y), h2 = pk1(hv.z), h3 = pk1(hv.w);
        ulonglong2 w01 = *reinterpret_cast<const ulonglong2*>(ws + ci*8);
        ulonglong2 w23 = *reinterpret_cast<const ulonglong2*>(ws + ci*8 + 4);
        fma2(acc[0][0], w01.x, h0); fma2(acc[0][1], w01.y, h0); fma2(acc[0][2], w23.x, h0); fma2(acc[0][3], w23.y, h0);
        fma2(acc[1][0], w01.x, h1); fma2(acc[1][1], w01.y, h1); fma2(acc[1][2], w23.x, h1); fma2(acc[1][3], w23.y, h1);
        fma2(acc[2][0], w01.x, h2); fma2(acc[2][1], w01.y, h2); fma2(acc[2][2], w23.x, h2); fma2(acc[2][3], w23.y, h2);
        fma2(acc[3][0], w01.x, h3); fma2(acc[3][1], w01.y, h3); fma2(acc[3][2], w23.x, h3); fma2(acc[3][3], w23.y, h3);
    }
    store4x8(acc, xp, 4096, false);
}

// ---------------- pre-VQ 1x1 conv: z_nhwc = W(64x128) @ relu(x) + b ----------------
__global__ void __launch_bounds__(256, 4)
vqc_k(const float* __restrict__ x, const float* __restrict__ w,
      const float* __restrict__ bias, float* __restrict__ z)
{
    __shared__ __align__(16) float ws[128 * 8];
    const int tid = threadIdx.x;
    const int cog = blockIdx.y;   // 8 groups of 8 (COUT=64)
    const int b   = blockIdx.z;
    for (int e = tid; e < 1024; e += 256) {
        int u = e & 7; int ci = e >> 3;
        ws[e] = w[(cog * 8 + u) * 128 + ci];
    }
    __syncthreads();
    const int p4 = (blockIdx.x * 256 + tid) * 4;
    u64 acc[4][4];
    #pragma unroll
    for (int cp = 0; cp < 4; cp++) {
        u64 bp = pk(bias[cog*8 + 2*cp], bias[cog*8 + 2*cp + 1]);
        #pragma unroll
        for (int px = 0; px < 4; px++) acc[px][cp] = bp;
    }
    const float* xb = x + (size_t)b * 128 * 4096 + p4;
    #pragma unroll 2
    for (int ci = 0; ci < 128; ci++) {
        float4 xv = relu4(*reinterpret_cast<const float4*>(xb + (size_t)ci * 4096));
        u64 x0 = pk1(xv.x), x1 = pk1(xv.y), x2 = pk1(xv.z), x3 = pk1(xv.w);
        ulonglong2 w01 = *reinterpret_cast<const ulonglong2*>(ws + ci*8);
        ulonglong2 w23 = *reinterpret_cast<const ulonglong2*>(ws + ci*8 + 4);
        fma2(acc[0][0], w01.x, x0); fma2(acc[0][1], w01.y, x0); fma2(acc[0][2], w23.x, x0); fma2(acc[0][3], w23.y, x0);
        fma2(acc[1][0], w01.x, x1); fma2(acc[1][1], w01.y, x1); fma2(acc[1][2], w23.x, x1); fma2(acc[1][3], w23.y, x1);
        fma2(acc[2][0], w01.x, x2); fma2(acc[2][1], w01.y, x2); fma2(acc[2][2], w23.x, x2); fma2(acc[2][3], w23.y, x2);
        fma2(acc[3][0], w01.x, x3); fma2(acc[3][1], w01.y, x3); fma2(acc[3][2], w23.x, x3); fma2(acc[3][3], w23.y, x3);
    }
    const size_t row0 = (size_t)b * 4096 + p4;
    #pragma unroll
    for (int px = 0; px < 4; px++) {
        float4 o0, o1;
        upk(acc[px][0], o0.x, o0.y); upk(acc[px][1], o0.z, o0.w);
        upk(acc[px][2], o1.x, o1.y); upk(acc[px][3], o1.z, o1.w);
        float* zp = z + (row0 + px) * 64 + cog * 8;
        *reinterpret_cast<float4*>(zp)     = o0;
        *reinterpret_cast<float4*>(zp + 4) = o1;
    }
}

// ---------------- VQ: argmin over 64 codes; 64 rows per block ----------------
__global__ void __launch_bounds__(64)
vq_k(const float* __restrict__ z, const float* __restrict__ emb,
     int* __restrict__ idx, float* __restrict__ ssep, int* __restrict__ cnt)
{
    __shared__ float es[4096];   // [k][d]
    __shared__ float zs[4096];   // transposed [d][r]
    __shared__ float en[64];
    __shared__ int   hist[64];
    __shared__ float er[64];
    const int tid = threadIdx.x;
    for (int e = tid; e < 4096; e += 64) es[e] = emb[e];
    hist[tid] = 0;
    const size_t base = (size_t)blockIdx.x * 64;
    for (int e = tid; e < 4096; e += 64) {
        int r = e >> 6, d = e & 63;
        zs[d * 64 + r] = z[base * 64 + e];
    }
    __syncthreads();
    {
        float s = 0.f;
        const float* ek = es + tid * 64;
        #pragma unroll 8
        for (int d = 0; d < 64; d++) s += ek[d] * ek[d];
        en[tid] = s;
    }
    __syncthreads();
    float best = 3.4e38f; int bk = 0;
    for (int k = 0; k < 64; k++) {
        float dot = 0.f;
        const float* ek = es + k * 64;
        #pragma unroll 8
        for (int d = 0; d < 64; d++) dot += zs[d * 64 + tid] * ek[d];
        float dist = en[k] - 2.f * dot;   // ||z||^2 dropped: constant per row
        if (dist < best) { best = dist; bk = k; }
    }
    idx[base + tid] = bk;
    atomicAdd(&hist[bk], 1);
    float e2 = 0.f;
    const float* ek = es + bk * 64;
    #pragma unroll 8
    for (int d = 0; d < 64; d++) {
        float df = zs[d * 64 + tid] - ek[d];
        e2 += df * df;
    }
    er[tid] = e2;
    __syncthreads();
    for (int s = 32; s > 0; s >>= 1) {
        if (tid < s) er[tid] += er[tid + s];
        __syncthreads();
    }
    if (tid == 0) ssep[blockIdx.x] = er[0];
    if (hist[tid] > 0) atomicAdd(&cnt[tid], hist[tid]);
}

// ---------------- scatter qn (NCHW) from indices; dual write (out + aligned) ----------------
__global__ void __launch_bounds__(256)
scatter_k(const int* __restrict__ idx, const float* __restrict__ emb,
          float* __restrict__ qn, float* __restrict__ qn2)
{
    const int i = blockIdx.x * 256 + threadIdx.x;   // 8,388,608 exact
    const int w = i & 63;
    const int h = (i >> 6) & 63;
    const int c = (i >> 12) & 63;
    const int b = i >> 18;
    const int r = (b << 12) | (h << 6) | w;
    float v = emb[idx[r] * 64 + c];
    qn[i]  = v;
    qn2[i] = v;
}

// ---------------- loss & perplexity ----------------
__global__ void init_k(int* __restrict__ cnt) {
    if (threadIdx.x < 64) cnt[threadIdx.x] = 0;
}

__global__ void __launch_bounds__(128)
finalize_k(const float* __restrict__ ssep, const int* __restrict__ cnt,
           float* __restrict__ out_loss, float* __restrict__ out_perp)
{
    __shared__ float s[128];
    const int tid = threadIdx.x;
    float a = 0.f;
    for (int i = tid; i < 2048; i += 128) a += ssep[i];
    s[tid] = a;
    __syncthreads();
    for (int st = 64; st > 0; st >>= 1) {
        if (tid < st) s[tid] += s[tid + st];
        __syncthreads();
    }
    if (tid == 0) {
        *out_loss = 1.25f * s[0] / 8388608.f;   // (1 + BETA) * mean((q - z)^2)
        float H = 0.f;
        for (int k = 0; k < 64; k++) {
            float p = (float)cnt[k] / 131072.f;
            H += p * logf(p + 1e-10f);
        }
        *out_perp = expf(-H);
    }
}

// ---------------- dec_c1 weight transform: deconv(s=1,k=3,p=1) -> conv OIHW ----------------
__global__ void wtrans_k(const float* __restrict__ w, float* __restrict__ wt)
{
    const int i = blockIdx.x * 256 + threadIdx.x;
    if (i >= 128 * 64 * 9) return;
    const int tap = i % 9;
    const int ci  = (i / 9) % 64;
    const int co  = i / (9 * 64);
    const int a = tap / 3, b2 = tap % 3;
    wt[i] = w[((size_t)ci * 128 + co) * 9 + (2 - a) * 3 + (2 - b2)];
}

// ---------------- dec_c2 deconv k=4 s=2 p=1: 128->64 at 64->128; 4 co x 8 px ----------------
__global__ void __launch_bounds__(256, 3)
deconv_c2_k(const float* __restrict__ in, const float* __restrict__ w,
            const float* __restrict__ bias, float* __restrict__ out)
{
    __shared__ __align__(16) float ws[128 * 64];   // [ci][16tap][4co]
    const int tid = threadIdx.x;
    const int cog = blockIdx.y;   // 16 groups of 4 co
    const int b   = blockIdx.z;
    for (int e = tid; e < 128 * 64; e += 256) {
        int u = e & 3; int rest = e >> 2; int tap = rest & 15; int ci = rest >> 4;
        ws[e] = w[((size_t)ci * 64 + cog * 4 + u) * 16 + tap];
    }
    __syncthreads();
    const int t   = blockIdx.x * 256 + tid;
    const int p8  = t * 8;
    const int oh  = p8 >> 7;          // HOUT=128
    const int ow8 = p8 & 127;
    const int ph  = (oh + 1) & 1;
    const int ihA = (oh + 1 - ph) >> 1;   // kh = ph
    const int ihB = ihA - 1;              // kh = ph+2
    const bool okA = (unsigned)ihA < 64u;
    const bool okB = (unsigned)ihB < 64u;
    const int iw0 = (ow8 >> 1) - 1;
    u64 acc[8][2];
    {
        u64 b0 = pk(bias[cog*4],   bias[cog*4+1]);
        u64 b1 = pk(bias[cog*4+2], bias[cog*4+3]);
        #pragma unroll
        for (int px = 0; px < 8; px++) { acc[px][0] = b0; acc[px][1] = b1; }
    }
    const float* inb = in + (size_t)b * 128 * 4096;
    for (int ci = 0; ci < 128; ci++) {
        const float* inc = inb + ci * 4096;
        u64 vA[6], vB[6];
        #pragma unroll
        for (int j = 0; j < 6; j++) { vA[j] = 0ull; vB[j] = 0ull; }
        if (okA) {
            const float* rp = inc + ihA * 64;
            float f0 = (iw0 >= 0) ? fmaxf(rp[iw0], 0.f) : 0.f;
            float4 c = relu4(*reinterpret_cast<const float4*>(rp + iw0 + 1));
            float f5 = (iw0 + 5 < 64) ? fmaxf(rp[iw0+5], 0.f) : 0.f;
            vA[0]=pk1(f0); vA[1]=pk1(c.x); vA[2]=pk1(c.y); vA[3]=pk1(c.z); vA[4]=pk1(c.w); vA[5]=pk1(f5);
        }
        if (okB) {
            const float* rp = inc + ihB * 64;
            float f0 = (iw0 >= 0) ? fmaxf(rp[iw0], 0.f) : 0.f;
            float4 c = relu4(*reinterpret_cast<const float4*>(rp + iw0 + 1));
            float f5 = (iw0 + 5 < 64) ? fmaxf(rp[iw0+5], 0.f) : 0.f;
            vB[0]=pk1(f0); vB[1]=pk1(c.x); vB[2]=pk1(c.y); vB[3]=pk1(c.z); vB[4]=pk1(c.w); vB[5]=pk1(f5);
        }
        const float* wc = ws + ci * 64;
        #pragma unroll
        for (int kw = 0; kw < 4; kw++) {
            ulonglong2 wA = *reinterpret_cast<const ulonglong2*>(wc + (ph*4 + kw) * 4);
            ulonglong2 wB = *reinterpret_cast<const ulonglong2*>(wc + ((ph+2)*4 + kw) * 4);
            #pragma unroll
            for (int i2 = 0; i2 < 4; i2++) {
                const int px = ((kw + 1) & 1) + 2 * i2;     // compile-time
                const int pw = kw & 1;
                const int j  = (kw < 2) ? (1 + ((px + 1 - pw) >> 1)) : ((px + 1 - pw) >> 1);
                u64 a = vA[j], c = vB[j];
                fma2(acc[px][0], wA.x, a); fma2(acc[px][1], wA.y, a);
                fma2(acc[px][0], wB.x, c); fma2(acc[px][1], wB.y, c);
            }
        }
    }
    float* op = out + ((size_t)b * 64 + cog * 4) * 16384 + p8;
    #pragma unroll
    for (int cp = 0; cp < 2; cp++) {
        float4 a0, a1, c0, c1;
        upk(acc[0][cp], a0.x, c0.x); upk(acc[1][cp], a0.y, c0.y);
        upk(acc[2][cp], a0.z, c0.z); upk(acc[3][cp], a0.w, c0.w);
        upk(acc[4][cp], a1.x, c1.x); upk(acc[5][cp], a1.y, c1.y);
        upk(acc[6][cp], a1.z, c1.z); upk(acc[7][cp], a1.w, c1.w);
        a0 = relu4(a0); a1 = relu4(a1); c0 = relu4(c0); c1 = relu4(c1);
        float* q0 = op + (size_t)(2*cp)   * 16384;
        float* q1 = op + (size_t)(2*cp+1) * 16384;
        *reinterpret_cast<float4*>(q0)     = a0;
        *reinterpret_cast<float4*>(q0 + 4) = a1;
        *reinterpret_cast<float4*>(q1)     = c0;
        *reinterpret_cast<float4*>(q1 + 4) = c1;
    }
}

// ---------------- dec_c3 deconv k=4 s=2 p=1: 64->1 at 128->256; tanh; 8 px ----------------
__global__ void __launch_bounds__(256)
deconv_c3_k(const float* __restrict__ in, const float* __restrict__ w,
            const float* __restrict__ bias, float* __restrict__ out)
{
    __shared__ float ws[64 * 16];
    const int tid = threadIdx.x;
    const int b   = blockIdx.z;
    for (int e = tid; e < 1024; e += 256) ws[e] = w[e];   // (64,1,4,4) -> [ci][tap]
    __syncthreads();
    const int t   = blockIdx.x * 256 + tid;
    const int p8  = t * 8;
    const int oh  = p8 >> 8;          // HOUT=256
    const int ow8 = p8 & 255;
    const int ph  = (oh + 1) & 1;
    const int ihA = (oh + 1 - ph) >> 1;
    const int ihB = ihA - 1;
    const bool okA = (unsigned)ihA < 128u;
    const bool okB = (unsigned)ihB < 128u;
    const int iw0 = (ow8 >> 1) - 1;
    float acc[8];
    #pragma unroll
    for (int px = 0; px < 8; px++) acc[px] = bias[0];
    const float* inb = in + (size_t)b * 64 * 16384;
    for (int ci = 0; ci < 64; ci++) {
        const float* inc = inb + ci * 16384;
        float vA[6], vB[6];
        #pragma unroll
        for (int j = 0; j < 6; j++) { vA[j] = 0.f; vB[j] = 0.f; }
        if (okA) {
            const float* rp = inc + ihA * 128;
            vA[0] = (iw0 >= 0) ? rp[iw0] : 0.f;
            float4 c = *reinterpret_cast<const float4*>(rp + iw0 + 1);
            vA[1] = c.x; vA[2] = c.y; vA[3] = c.z; vA[4] = c.w;
            vA[5] = (iw0 + 5 < 128) ? rp[iw0+5] : 0.f;
        }
        if (okB) {
            const float* rp = inc + ihB * 128;
            vB[0] = (iw0 >= 0) ? rp[iw0] : 0.f;
            float4 c = *reinterpret_cast<const float4*>(rp + iw0 + 1);
            vB[1] = c.x; vB[2] = c.y; vB[3] = c.z; vB[4] = c.w;
            vB[5] = (iw0 + 5 < 128) ? rp[iw0+5] : 0.f;
        }
        const float* wc = ws + ci * 16;
        #pragma unroll
        for (int kw = 0; kw < 4; kw++) {
            float fA = wc[ph*4 + kw];
            float fB = wc[(ph+2)*4 + kw];
            #pragma unroll
            for (int i2 = 0; i2 < 4; i2++) {
                const int px = ((kw + 1) & 1) + 2 * i2;
                const int pw = kw & 1;
                const int j  = (kw < 2) ? (1 + ((px + 1 - pw) >> 1)) : ((px + 1 - pw) >> 1);
                acc[px] = fmaf(fA, vA[j], acc[px]);
                acc[px] = fmaf(fB, vB[j], acc[px]);
            }
        }
    }
    float* op = out + (size_t)b * 65536 + p8;   // out base offset 1 -> scalar stores
    #pragma unroll
    for (int px = 0; px < 8; px++) op[px] = tanhf(acc[px]);
}

// ---------------- launch ----------------
extern "C" void kernel_launch(void* const* d_in, const int* in_sizes, int n_in,
                              void* d_out, int out_size)
{
    const float* x        = (const float*)d_in[0];
    const float* enc_c1_w = (const float*)d_in[1];
    const float* enc_c1_b = (const float*)d_in[2];
    const float* enc_c2_w = (const float*)d_in[3];
    const float* enc_c2_b = (const float*)d_in[4];
    const float* enc_c3_w = (const float*)d_in[5];
    const float* enc_c3_b = (const float*)d_in[6];
    const float* enc_r1_w = (const float*)d_in[7];
    const float* enc_r2_w = (const float*)d_in[8];
    const float* vqc_w    = (const float*)d_in[9];
    const float* vqc_b    = (const float*)d_in[10];
    const float* emb      = (const float*)d_in[11];
    const float* dec_c1_w = (const float*)d_in[12];
    const float* dec_c1_b = (const float*)d_in[13];
    const float* dec_r1_w = (const float*)d_in[14];
    const float* dec_r2_w = (const float*)d_in[15];
    const float* dec_c2_w = (const float*)d_in[16];
    const float* dec_c2_b = (const float*)d_in[17];
    const float* dec_c3_w = (const float*)d_in[18];
    const float* dec_c3_b = (const float*)d_in[19];
    float* out = (float*)d_out;

    float *p_big, *p_x, *p_y, *p_h, *p_z, *p_w1t, *p_ssep;
    int *p_idx, *p_cnt;
    cudaGetSymbolAddress((void**)&p_big,  g_big);
    cudaGetSymbolAddress((void**)&p_x,    g_x);
    cudaGetSymbolAddress((void**)&p_y,    g_y);
    cudaGetSymbolAddress((void**)&p_h,    g_h);
    cudaGetSymbolAddress((void**)&p_z,    g_z);
    cudaGetSymbolAddress((void**)&p_w1t,  g_w1t);
    cudaGetSymbolAddress((void**)&p_ssep, g_ssep);
    cudaGetSymbolAddress((void**)&p_idx,  g_idx);
    cudaGetSymbolAddress((void**)&p_cnt,  g_cnt);

    // ---- encoder ----
    conv_k4s2<1, 64, 256, true><<<dim3(16, 8, 32), 256>>>(x, enc_c1_w, enc_c1_b, p_big);
    conv_k4s2<64, 128, 128, true><<<dim3(4, 16, 32), 256>>>(p_big, enc_c2_w, enc_c2_b, p_x);
    conv3x3_k<128, 128, false, false, true><<<dim3(4, 16, 32), 256>>>(p_x, enc_c3_w, enc_c3_b, p_y);
    for (int it = 0; it < 2; it++) {
        conv3x3_k<128, 64, true, true, false><<<dim3(4, 8, 32), 256>>>(p_y, enc_r1_w, nullptr, p_h);
        res_add_k<<<dim3(4, 16, 32), 256>>>(p_y, p_h, enc_r2_w);
    }
    vqc_k<<<dim3(4, 8, 32), 256>>>(p_y, vqc_w, vqc_b, p_z);

    // ---- VQ ----
    init_k<<<1, 64>>>(p_cnt);
    vq_k<<<2048, 64>>>(p_z, emb, p_idx, p_ssep, p_cnt);
    // scatter writes qn into d_out (8B-aligned only) AND an aligned copy into g_z
    scatter_k<<<32768, 256>>>(p_idx, emb, out + OFF_QN, p_z);
    finalize_k<<<1, 128>>>(p_ssep, p_cnt, out, out + OFF_PERP);

    // ---- decoder ----
    wtrans_k<<<288, 256>>>(dec_c1_w, p_w1t);
    conv3x3_k<64, 128, false, false, true><<<dim3(4, 16, 32), 256>>>(p_z, p_w1t, dec_c1_b, p_y);
    for (int it = 0; it < 2; it++) {
        conv3x3_k<128, 64, true, true, false><<<dim3(4, 8, 32), 256>>>(p_y, dec_r1_w, nullptr, p_h);
        res_add_k<<<dim3(4, 16, 32), 256>>>(p_y, p_h, dec_r2_w);
    }
    deconv_c2_k<<<dim3(8, 16, 32), 256>>>(p_y, dec_c2_w, dec_c2_b, p_big);
    deconv_c3_k<<<dim3(32, 1, 32), 256>>>(p_big, dec_c3_w, dec_c3_b, out + OFF_XRE);
}

// round 17
// speedup vs baseline: 1.0287x; 1.0287x over previous
#include <cuda_runtime.h>
#include <math.h>

// ---------------- problem constants ----------------
// B=32, HID=128, RES=64, K=D=64
// out layout: [0]=loss, [1..2097152]=x_re, [2097153]=perplexity, [2097154..]=qn
#define OFF_XRE   1
#define OFF_PERP  2097153
#define OFF_QN    2097154

// ---------------- scratch (device globals; no allocation) ----------------
__device__ float g_big[33554432];   // 32*64*128*128 : enc_c1 out, dec_c2 out
__device__ float g_x  [16777216];   // 32*128*64*64  : enc_c2 out
__device__ float g_y  [16777216];   // 32*128*64*64  : res-block state s=relu(x) (enc & dec)
__device__ float g_h  [ 8388608];   // 32*64*64*64   : res intermediate
__device__ float g_z  [ 8388608];   // z NHWC rows; reused as ALIGNED qn copy after VQ
__device__ int   g_idx[131072];
__device__ float g_w1t[128*64*9];   // transformed dec_c1 weights (OIHW conv form)
__device__ float g_ssep[2048];
__device__ int   g_cnt[64];

// ---------------- packed f32x2 helpers ----------------
using u64 = unsigned long long;

__device__ __forceinline__ u64 pk(float a, float b) {
    u64 r; asm("mov.b64 %0,{%1,%2};" : "=l"(r) : "f"(a), "f"(b)); return r;
}
__device__ __forceinline__ u64 pk1(float a) {
    u64 r; asm("mov.b64 %0,{%1,%1};" : "=l"(r) : "f"(a)); return r;
}
__device__ __forceinline__ void upk(u64 v, float& a, float& b) {
    asm("mov.b64 {%0,%1},%2;" : "=f"(a), "=f"(b) : "l"(v));
}
__device__ __forceinline__ void fma2(u64& d, u64 a, u64 b) {
    asm("fma.rn.f32x2 %0,%1,%2,%0;" : "+l"(d) : "l"(a), "l"(b));
}
__device__ __forceinline__ float4 relu4(float4 v) {
    v.x = fmaxf(v.x, 0.f); v.y = fmaxf(v.y, 0.f);
    v.z = fmaxf(v.z, 0.f); v.w = fmaxf(v.w, 0.f);
    return v;
}

// store acc[4px][4copair] to channel-major planes
__device__ __forceinline__ void store4x8(u64 acc[4][4], float* op, int plane, bool relu) {
    #pragma unroll
    for (int cp = 0; cp < 4; cp++) {
        float4 o0, o1;
        upk(acc[0][cp], o0.x, o1.x);
        upk(acc[1][cp], o0.y, o1.y);
        upk(acc[2][cp], o0.z, o1.z);
        upk(acc[3][cp], o0.w, o1.w);
        if (relu) { o0 = relu4(o0); o1 = relu4(o1); }
        *reinterpret_cast<float4*>(op + (size_t)(2*cp)   * plane) = o0;
        *reinterpret_cast<float4*>(op + (size_t)(2*cp+1) * plane) = o1;
    }
}

// ---------------- conv k=4 s=2 p=1, 8 co x 4 px per thread ----------------
template<int CIN, int COUT, int HIN, bool RELU_OUT>
__global__ void __launch_bounds__(256, 3)
conv_k4s2(const float* __restrict__ in, const float* __restrict__ w,
          const float* __restrict__ bias, float* __restrict__ out)
{
    constexpr int HOUT = HIN / 2;
    __shared__ __align__(16) float ws[CIN * 128];
    const int tid = threadIdx.x;
    const int cog = blockIdx.y;
    const int b   = blockIdx.z;
    for (int e = tid; e < CIN * 128; e += 256) {
        int u = e & 7; int rest = e >> 3; int tap = rest & 15; int ci = rest >> 4;
        ws[e] = w[((size_t)(cog * 8 + u) * CIN + ci) * 16 + tap];
    }
    __syncthreads();
    const int t   = blockIdx.x * 256 + tid;
    const int p4  = t * 4;
    const int oh  = p4 / HOUT;
    const int ow4 = p4 % HOUT;
    u64 acc[4][4];
    #pragma unroll
    for (int cp = 0; cp < 4; cp++) {
        u64 bp = pk(bias[cog*8 + 2*cp], bias[cog*8 + 2*cp + 1]);
        #pragma unroll
        for (int px = 0; px < 4; px++) acc[px][cp] = bp;
    }
    const float* inb = in + (size_t)b * CIN * HIN * HIN;
    for (int ci = 0; ci < CIN; ci++) {
        const float* inc = inb + (size_t)ci * HIN * HIN;
        const float* wc  = ws + ci * 128;
        #pragma unroll
        for (int kh = 0; kh < 4; kh++) {
            int ih = oh * 2 + kh - 1;
            if ((unsigned)ih >= (unsigned)HIN) continue;
            const float* rp = inc + ih * HIN + ow4 * 2;
            float vl = (ow4 > 0) ? rp[-1] : 0.f;
            float4 c0 = *reinterpret_cast<const float4*>(rp);
            float4 c1 = *reinterpret_cast<const float4*>(rp + 4);
            float vr = (ow4 < HOUT - 4) ? rp[8] : 0.f;
            u64 v[10] = { pk1(vl), pk1(c0.x), pk1(c0.y), pk1(c0.z), pk1(c0.w),
                          pk1(c1.x), pk1(c1.y), pk1(c1.z), pk1(c1.w), pk1(vr) };
            #pragma unroll
            for (int kw = 0; kw < 4; kw++) {
                ulonglong2 w01 = *reinterpret_cast<const ulonglong2*>(wc + (kh*4+kw)*8);
                ulonglong2 w23 = *reinterpret_cast<const ulonglong2*>(wc + (kh*4+kw)*8 + 4);
                #pragma unroll
                for (int px = 0; px < 4; px++) {
                    u64 xv = v[2*px + kw];
                    fma2(acc[px][0], w01.x, xv);
                    fma2(acc[px][1], w01.y, xv);
                    fma2(acc[px][2], w23.x, xv);
                    fma2(acc[px][3], w23.y, xv);
                }
            }
        }
    }
    float* op = out + ((size_t)b * COUT + cog * 8) * (HOUT * HOUT) + p4;
    store4x8(acc, op, HOUT * HOUT, RELU_OUT);
}

// ---------------- conv 3x3 s=1 p=1 at 64x64, 8 co x 4 px per thread ----------------
// (256,4): proven best config (R11). Inputs are pre-relu'd upstream (s = relu(x) stored).
template<int CIN, int COUT, bool RELU_OUT, bool BIAS>
__global__ void __launch_bounds__(256, 4)
conv3x3_k(const float* __restrict__ in, const float* __restrict__ w,
          const float* __restrict__ bias, float* __restrict__ out)
{
    __shared__ __align__(16) float ws[CIN * 72];
    const int tid = threadIdx.x;
    const int cog = blockIdx.y;
    const int b   = blockIdx.z;
    for (int e = tid; e < CIN * 72; e += 256) {
        int u = e & 7; int rest = e >> 3; int tap = rest % 9; int ci = rest / 9;
        ws[e] = w[((size_t)(cog * 8 + u) * CIN + ci) * 9 + tap];
    }
    __syncthreads();
    const int t   = blockIdx.x * 256 + tid;   // 0..1023
    const int oh  = t >> 4;
    const int ow4 = (t & 15) << 2;
    u64 acc[4][4];
    #pragma unroll
    for (int cp = 0; cp < 4; cp++) {
        u64 bp = BIAS ? pk(bias[cog*8 + 2*cp], bias[cog*8 + 2*cp + 1]) : 0ull;
        #pragma unroll
        for (int px = 0; px < 4; px++) acc[px][cp] = bp;
    }
    const float* inb = in + (size_t)b * CIN * 4096;
    for (int ci = 0; ci < CIN; ci++) {
        const float* inc = inb + ci * 4096;
        const float* wc  = ws + ci * 72;
        #pragma unroll
        for (int kh = 0; kh < 3; kh++) {
            int ih = oh + kh - 1;
            if ((unsigned)ih >= 64u) continue;
            const float* rp = inc + ih * 64 + ow4;
            float vl = (ow4 > 0)  ? rp[-1] : 0.f;
            float4 c  = *reinterpret_cast<const float4*>(rp);
            float vr = (ow4 < 60) ? rp[4]  : 0.f;
            u64 v[6] = { pk1(vl), pk1(c.x), pk1(c.y), pk1(c.z), pk1(c.w), pk1(vr) };
            #pragma unroll
            for (int kw = 0; kw < 3; kw++) {
                ulonglong2 w01 = *reinterpret_cast<const ulonglong2*>(wc + (kh*3+kw)*8);
                ulonglong2 w23 = *reinterpret_cast<const ulonglong2*>(wc + (kh*3+kw)*8 + 4);
                #pragma unroll
                for (int px = 0; px < 4; px++) {
                    u64 xv = v[px + kw];
                    fma2(acc[px][0], w01.x, xv);
                    fma2(acc[px][1], w01.y, xv);
                    fma2(acc[px][2], w23.x, xv);
                    fma2(acc[px][3], w23.y, xv);
                }
            }
        }
    }
    float* op = out + ((size_t)b * COUT + cog * 8) * 4096 + (oh * 64 + ow4);
    store4x8(acc, op, 4096, RELU_OUT);
}

// ---------------- residual add: s_new = relu(s + W2(128x64) @ h) ----------------
// x already holds s = relu(prev); skip term needs no relu. Store relu'd state.
__global__ void __launch_bounds__(256, 4)
res_add_k(float* __restrict__ x, const float* __restrict__ h,
          const float* __restrict__ w2)
{
    __shared__ __align__(16) float ws[64 * 8];
    const int tid = threadIdx.x;
    const int cog = blockIdx.y;   // 16 groups of 8 (COUT=128)
    const int b   = blockIdx.z;
    for (int e = tid; e < 512; e += 256) {
        int u = e & 7; int ci = e >> 3;
        ws[e] = w2[(cog * 8 + u) * 64 + ci];
    }
    __syncthreads();
    const int p4 = (blockIdx.x * 256 + tid) * 4;
    float* xp = x + ((size_t)b * 128 + cog * 8) * 4096 + p4;
    u64 acc[4][4];
    #pragma unroll
    for (int cp = 0; cp < 4; cp++) {
        float4 a = *reinterpret_cast<const float4*>(xp + (size_t)(2*cp)   * 4096);
        float4 c = *reinterpret_cast<const float4*>(xp + (size_t)(2*cp+1) * 4096);
        acc[0][cp] = pk(a.x, c.x); acc[1][cp] = pk(a.y, c.y);
        acc[2][cp] = pk(a.z, c.z); acc[3][cp] = pk(a.w, c.w);
    }
    const float* hb = h + (size_t)b * 64 * 4096 + p4;
    #pragma unroll 2
    for (int ci = 0; ci < 64; ci++) {
        float4 hv = *reinterpret_cast<const float4*>(hb + (size_t)ci * 4096);
        u64 h0 = pk1(hv.x), h1 = pk1(hv.y), h2 = pk1(hv.z), h3 = pk1(hv.w);
        ulonglong2 w01 = *reinterpret_cast<const ulonglong2*>(ws + ci*8);
        ulonglong2 w23 = *reinterpret_cast<const ulonglong2*>(ws + ci*8 + 4);
        fma2(acc[0][0], w01.x, h0); fma2(acc[0][1], w01.y, h0); fma2(acc[0][2], w23.x, h0); fma2(acc[0][3], w23.y, h0);
        fma2(acc[1][0], w01.x, h1); fma2(acc[1][1], w01.y, h1); fma2(acc[1][2], w23.x, h1); fma2(acc[1][3], w23.y, h1);
        fma2(acc[2][0], w01.x, h2); fma2(acc[2][1], w01.y, h2); fma2(acc[2][2], w23.x, h2); fma2(acc[2][3], w23.y, h2);
        fma2(acc[3][0], w01.x, h3); fma2(acc[3][1], w01.y, h3); fma2(acc[3][2], w23.x, h3); fma2(acc[3][3], w23.y, h3);
    }
    store4x8(acc, xp, 4096, true);   // store s = relu(x)
}

// ---------------- pre-VQ 1x1 conv: z_nhwc = W(64x128) @ s + b (s pre-relu'd) ----------------
__global__ void __launch_bounds__(256, 4)
vqc_k(const float* __restrict__ x, const float* __restrict__ w,
      const float* __restrict__ bias, float* __restrict__ z)
{
    __shared__ __align__(16) float ws[128 * 8];
    const int tid = threadIdx.x;
    const int cog = blockIdx.y;   // 8 groups of 8 (COUT=64)
    const int b   = blockIdx.z;
    for (int e = tid; e < 1024; e += 256) {
        int u = e & 7; int ci = e >> 3;
        ws[e] = w[(cog * 8 + u) * 128 + ci];
    }
    __syncthreads();
    const int p4 = (blockIdx.x * 256 + tid) * 4;
    u64 acc[4][4];
    #pragma unroll
    for (int cp = 0; cp < 4; cp++) {
        u64 bp = pk(bias[cog*8 + 2*cp], bias[cog*8 + 2*cp + 1]);
        #pragma unroll
        for (int px = 0; px < 4; px++) acc[px][cp] = bp;
    }
    const float* xb = x + (size_t)b * 128 * 4096 + p4;
    #pragma unroll 2
    for (int ci = 0; ci < 128; ci++) {
        float4 xv = *reinterpret_cast<const float4*>(xb + (size_t)ci * 4096);
        u64 x0 = pk1(xv.x), x1 = pk1(xv.y), x2 = pk1(xv.z), x3 = pk1(xv.w);
        ulonglong2 w01 = *reinterpret_cast<const ulonglong2*>(ws + ci*8);
        ulonglong2 w23 = *reinterpret_cast<const ulonglong2*>(ws + ci*8 + 4);
        fma2(acc[0][0], w01.x, x0); fma2(acc[0][1], w01.y, x0); fma2(acc[0][2], w23.x, x0); fma2(acc[0][3], w23.y, x0);
        fma2(acc[1][0], w01.x, x1); fma2(acc[1][1], w01.y, x1); fma2(acc[1][2], w23.x, x1); fma2(acc[1][3], w23.y, x1);
        fma2(acc[2][0], w01.x, x2); fma2(acc[2][1], w01.y, x2); fma2(acc[2][2], w23.x, x2); fma2(acc[2][3], w23.y, x2);
        fma2(acc[3][0], w01.x, x3); fma2(acc[3][1], w01.y, x3); fma2(acc[3][2], w23.x, x3); fma2(acc[3][3], w23.y, x3);
    }
    const size_t row0 = (size_t)b * 4096 + p4;
    #pragma unroll
    for (int px = 0; px < 4; px++) {
        float4 o0, o1;
        upk(acc[px][0], o0.x, o0.y); upk(acc[px][1], o0.z, o0.w);
        upk(acc[px][2], o1.x, o1.y); upk(acc[px][3], o1.z, o1.w);
        float* zp = z + (row0 + px) * 64 + cog * 8;
        *reinterpret_cast<float4*>(zp)     = o0;
        *reinterpret_cast<float4*>(zp + 4) = o1;
    }
}

// ---------------- VQ: argmin over 64 codes; 64 rows per block ----------------
__global__ void __launch_bounds__(64)
vq_k(const float* __restrict__ z, const float* __restrict__ emb,
     int* __restrict__ idx, float* __restrict__ ssep, int* __restrict__ cnt)
{
    __shared__ float es[4096];   // [k][d]
    __shared__ float zs[4096];   // transposed [d][r]
    __shared__ float en[64];
    __shared__ int   hist[64];
    __shared__ float er[64];
    const int tid = threadIdx.x;
    for (int e = tid; e < 4096; e += 64) es[e] = emb[e];
    hist[tid] = 0;
    const size_t base = (size_t)blockIdx.x * 64;
    for (int e = tid; e < 4096; e += 64) {
        int r = e >> 6, d = e & 63;
        zs[d * 64 + r] = z[base * 64 + e];
    }
    __syncthreads();
    {
        float s = 0.f;
        const float* ek = es + tid * 64;
        #pragma unroll 8
        for (int d = 0; d < 64; d++) s += ek[d] * ek[d];
        en[tid] = s;
    }
    __syncthreads();
    float best = 3.4e38f; int bk = 0;
    for (int k = 0; k < 64; k++) {
        float dot = 0.f;
        const float* ek = es + k * 64;
        #pragma unroll 8
        for (int d = 0; d < 64; d++) dot += zs[d * 64 + tid] * ek[d];
        float dist = en[k] - 2.f * dot;   // ||z||^2 dropped: constant per row
        if (dist < best) { best = dist; bk = k; }
    }
    idx[base + tid] = bk;
    atomicAdd(&hist[bk], 1);
    float e2 = 0.f;
    const float* ek = es + bk * 64;
    #pragma unroll 8
    for (int d = 0; d < 64; d++) {
        float df = zs[d * 64 + tid] - ek[d];
        e2 += df * df;
    }
    er[tid] = e2;
    __syncthreads();
    for (int s = 32; s > 0; s >>= 1) {
        if (tid < s) er[tid] += er[tid + s];
        __syncthreads();
    }
    if (tid == 0) ssep[blockIdx.x] = er[0];
    if (hist[tid] > 0) atomicAdd(&cnt[tid], hist[tid]);
}

// ---------------- scatter qn (NCHW) from indices; dual write (out + aligned) ----------------
__global__ void __launch_bounds__(256)
scatter_k(const int* __restrict__ idx, const float* __restrict__ emb,
          float* __restrict__ qn, float* __restrict__ qn2)
{
    const int i = blockIdx.x * 256 + threadIdx.x;   // 8,388,608 exact
    const int w = i & 63;
    const int h = (i >> 6) & 63;
    const int c = (i >> 12) & 63;
    const int b = i >> 18;
    const int r = (b << 12) | (h << 6) | w;
    float v = emb[idx[r] * 64 + c];
    qn[i]  = v;
    qn2[i] = v;
}

// ---------------- loss & perplexity ----------------
__global__ void init_k(int* __restrict__ cnt) {
    if (threadIdx.x < 64) cnt[threadIdx.x] = 0;
}

__global__ void __launch_bounds__(128)
finalize_k(const float* __restrict__ ssep, const int* __restrict__ cnt,
           float* __restrict__ out_loss, float* __restrict__ out_perp)
{
    __shared__ float s[128];
    const int tid = threadIdx.x;
    float a = 0.f;
    for (int i = tid; i < 2048; i += 128) a += ssep[i];
    s[tid] = a;
    __syncthreads();
    for (int st = 64; st > 0; st >>= 1) {
        if (tid < st) s[tid] += s[tid + st];
        __syncthreads();
    }
    if (tid == 0) {
        *out_loss = 1.25f * s[0] / 8388608.f;   // (1 + BETA) * mean((q - z)^2)
        float H = 0.f;
        for (int k = 0; k < 64; k++) {
            float p = (float)cnt[k] / 131072.f;
            H += p * logf(p + 1e-10f);
        }
        *out_perp = expf(-H);
    }
}

// ---------------- dec_c1 weight transform: deconv(s=1,k=3,p=1) -> conv OIHW ----------------
__global__ void wtrans_k(const float* __restrict__ w, float* __restrict__ wt)
{
    const int i = blockIdx.x * 256 + threadIdx.x;
    if (i >= 128 * 64 * 9) return;
    const int tap = i % 9;
    const int ci  = (i / 9) % 64;
    const int co  = i / (9 * 64);
    const int a = tap / 3, b2 = tap % 3;
    wt[i] = w[((size_t)ci * 128 + co) * 9 + (2 - a) * 3 + (2 - b2)];
}

// ---------------- dec_c2 deconv k=4 s=2 p=1: 128->64 at 64->128; 4 co x 8 px ----------------
// input is s = relu(res-block out), already relu'd — no relu on loads
__global__ void __launch_bounds__(256, 3)
deconv_c2_k(const float* __restrict__ in, const float* __restrict__ w,
            const float* __restrict__ bias, float* __restrict__ out)
{
    __shared__ __align__(16) float ws[128 * 64];   // [ci][16tap][4co]
    const int tid = threadIdx.x;
    const int cog = blockIdx.y;   // 16 groups of 4 co
    const int b   = blockIdx.z;
    for (int e = tid; e < 128 * 64; e += 256) {
        int u = e & 3; int rest = e >> 2; int tap = rest & 15; int ci = rest >> 4;
        ws[e] = w[((size_t)ci * 64 + cog * 4 + u) * 16 + tap];
    }
    __syncthreads();
    const int t   = blockIdx.x * 256 + tid;
    const int p8  = t * 8;
    const int oh  = p8 >> 7;          // HOUT=128
    const int ow8 = p8 & 127;
    const int ph  = (oh + 1) & 1;
    const int ihA = (oh + 1 - ph) >> 1;   // kh = ph
    const int ihB = ihA - 1;              // kh = ph+2
    const bool okA = (unsigned)ihA < 64u;
    const bool okB = (unsigned)ihB < 64u;
    const int iw0 = (ow8 >> 1) - 1;
    u64 acc[8][2];
    {
        u64 b0 = pk(bias[cog*4],   bias[cog*4+1]);
        u64 b1 = pk(bias[cog*4+2], bias[cog*4+3]);
        #pragma unroll
        for (int px = 0; px < 8; px++) { acc[px][0] = b0; acc[px][1] = b1; }
    }
    const float* inb = in + (size_t)b * 128 * 4096;
    for (int ci = 0; ci < 128; ci++) {
        const float* inc = inb + ci * 4096;
        u64 vA[6], vB[6];
        #pragma unroll
        for (int j = 0; j < 6; j++) { vA[j] = 0ull; vB[j] = 0ull; }
        if (okA) {
            const float* rp = inc + ihA * 64;
            float f0 = (iw0 >= 0) ? rp[iw0] : 0.f;
            float4 c = *reinterpret_cast<const float4*>(rp + iw0 + 1);
            float f5 = (iw0 + 5 < 64) ? rp[iw0+5] : 0.f;
            vA[0]=pk1(f0); vA[1]=pk1(c.x); vA[2]=pk1(c.y); vA[3]=pk1(c.z); vA[4]=pk1(c.w); vA[5]=pk1(f5);
        }
        if (okB) {
            const float* rp = inc + ihB * 64;
            float f0 = (iw0 >= 0) ? rp[iw0] : 0.f;
            float4 c = *reinterpret_cast<const float4*>(rp + iw0 + 1);
            float f5 = (iw0 + 5 < 64) ? rp[iw0+5] : 0.f;
            vB[0]=pk1(f0); vB[1]=pk1(c.x); vB[2]=pk1(c.y); vB[3]=pk1(c.z); vB[4]=pk1(c.w); vB[5]=pk1(f5);
        }
        const float* wc = ws + ci * 64;
        #pragma unroll
        for (int kw = 0; kw < 4; kw++) {
            ulonglong2 wA = *reinterpret_cast<const ulonglong2*>(wc + (ph*4 + kw) * 4);
            ulonglong2 wB = *reinterpret_cast<const ulonglong2*>(wc + ((ph+2)*4 + kw) * 4);
            #pragma unroll
            for (int i2 = 0; i2 < 4; i2++) {
                const int px = ((kw + 1) & 1) + 2 * i2;     // compile-time
                const int pw = kw & 1;
                const int j  = (kw < 2) ? (1 + ((px + 1 - pw) >> 1)) : ((px + 1 - pw) >> 1);
                u64 a = vA[j], c = vB[j];
                fma2(acc[px][0], wA.x, a); fma2(acc[px][1], wA.y, a);
                fma2(acc[px][0], wB.x, c); fma2(acc[px][1], wB.y, c);
            }
        }
    }
    float* op = out + ((size_t)b * 64 + cog * 4) * 16384 + p8;
    #pragma unroll
    for (int cp = 0; cp < 2; cp++) {
        float4 a0, a1, c0, c1;
        upk(acc[0][cp], a0.x, c0.x); upk(acc[1][cp], a0.y, c0.y);
        upk(acc[2][cp], a0.z, c0.z); upk(acc[3][cp], a0.w, c0.w);
        upk(acc[4][cp], a1.x, c1.x); upk(acc[5][cp], a1.y, c1.y);
        upk(acc[6][cp], a1.z, c1.z); upk(acc[7][cp], a1.w, c1.w);
        a0 = relu4(a0); a1 = relu4(a1); c0 = relu4(c0); c1 = relu4(c1);
        float* q0 = op + (size_t)(2*cp)   * 16384;
        float* q1 = op + (size_t)(2*cp+1) * 16384;
        *reinterpret_cast<float4*>(q0)     = a0;
        *reinterpret_cast<float4*>(q0 + 4) = a1;
        *reinterpret_cast<float4*>(q1)     = c0;
        *reinterpret_cast<float4*>(q1 + 4) = c1;
    }
}

// ---------------- dec_c3 deconv k=4 s=2 p=1: 64->1 at 128->256; tanh; 8 px ----------------
__global__ void __launch_bounds__(256)
deconv_c3_k(const float* __restrict__ in, const float* __restrict__ w,
            const float* __restrict__ bias, float* __restrict__ out)
{
    __shared__ float ws[64 * 16];
    const int tid = threadIdx.x;
    const int b   = blockIdx.z;
    for (int e = tid; e < 1024; e += 256) ws[e] = w[e];   // (64,1,4,4) -> [ci][tap]
    __syncthreads();
    const int t   = blockIdx.x * 256 + tid;
    const int p8  = t * 8;
    const int oh  = p8 >> 8;          // HOUT=256
    const int ow8 = p8 & 255;
    const int ph  = (oh + 1) & 1;
    const int ihA = (oh + 1 - ph) >> 1;
    const int ihB = ihA - 1;
    const bool okA = (unsigned)ihA < 128u;
    const bool okB = (unsigned)ihB < 128u;
    const int iw0 = (ow8 >> 1) - 1;
    float acc[8];
    #pragma unroll
    for (int px = 0; px < 8; px++) acc[px] = bias[0];
    const float* inb = in + (size_t)b * 64 * 16384;
    for (int ci = 0; ci < 64; ci++) {
        const float* inc = inb + ci * 16384;
        float vA[6], vB[6];
        #pragma unroll
        for (int j = 0; j < 6; j++) { vA[j] = 0.f; vB[j] = 0.f; }
        if (okA) {
            const float* rp = inc + ihA * 128;
            vA[0] = (iw0 >= 0) ? rp[iw0] : 0.f;
            float4 c = *reinterpret_cast<const float4*>(rp + iw0 + 1);
            vA[1] = c.x; vA[2] = c.y; vA[3] = c.z; vA[4] = c.w;
            vA[5] = (iw0 + 5 < 128) ? rp[iw0+5] : 0.f;
        }
        if (okB) {
            const float* rp = inc + ihB * 128;
            vB[0] = (iw0 >= 0) ? rp[iw0] : 0.f;
            float4 c = *reinterpret_cast<const float4*>(rp + iw0 + 1);
            vB[1] = c.x; vB[2] = c.y; vB[3] = c.z; vB[4] = c.w;
            vB[5] = (iw0 + 5 < 128) ? rp[iw0+5] : 0.f;
        }
        const float* wc = ws + ci * 16;
        #pragma unroll
        for (int kw = 0; kw < 4; kw++) {
            float fA = wc[ph*4 + kw];
            float fB = wc[(ph+2)*4 + kw];
            #pragma unroll
            for (int i2 = 0; i2 < 4; i2++) {
                const int px = ((kw + 1) & 1) + 2 * i2;
                const int pw = kw & 1;
                const int j  = (kw < 2) ? (1 + ((px + 1 - pw) >> 1)) : ((px + 1 - pw) >> 1);
                acc[px] = fmaf(fA, vA[j], acc[px]);
                acc[px] = fmaf(fB, vB[j], acc[px]);
            }
        }
    }
    float* op = out + (size_t)b * 65536 + p8;   // out base offset 1 -> scalar stores
    #pragma unroll
    for (int px = 0; px < 8; px++) op[px] = tanhf(acc[px]);
}

// ---------------- launch ----------------
extern "C" void kernel_launch(void* const* d_in, const int* in_sizes, int n_in,
                              void* d_out, int out_size)
{
    const float* x        = (const float*)d_in[0];
    const float* enc_c1_w = (const float*)d_in[1];
    const float* enc_c1_b = (const float*)d_in[2];
    const float* enc_c2_w = (const float*)d_in[3];
    const float* enc_c2_b = (const float*)d_in[4];
    const float* enc_c3_w = (const float*)d_in[5];
    const float* enc_c3_b = (const float*)d_in[6];
    const float* enc_r1_w = (const float*)d_in[7];
    const float* enc_r2_w = (const float*)d_in[8];
    const float* vqc_w    = (const float*)d_in[9];
    const float* vqc_b    = (const float*)d_in[10];
    const float* emb      = (const float*)d_in[11];
    const float* dec_c1_w = (const float*)d_in[12];
    const float* dec_c1_b = (const float*)d_in[13];
    const float* dec_r1_w = (const float*)d_in[14];
    const float* dec_r2_w = (const float*)d_in[15];
    const float* dec_c2_w = (const float*)d_in[16];
    const float* dec_c2_b = (const float*)d_in[17];
    const float* dec_c3_w = (const float*)d_in[18];
    const float* dec_c3_b = (const float*)d_in[19];
    float* out = (float*)d_out;

    float *p_big, *p_x, *p_y, *p_h, *p_z, *p_w1t, *p_ssep;
    int *p_idx, *p_cnt;
    cudaGetSymbolAddress((void**)&p_big,  g_big);
    cudaGetSymbolAddress((void**)&p_x,    g_x);
    cudaGetSymbolAddress((void**)&p_y,    g_y);
    cudaGetSymbolAddress((void**)&p_h,    g_h);
    cudaGetSymbolAddress((void**)&p_z,    g_z);
    cudaGetSymbolAddress((void**)&p_w1t,  g_w1t);
    cudaGetSymbolAddress((void**)&p_ssep, g_ssep);
    cudaGetSymbolAddress((void**)&p_idx,  g_idx);
    cudaGetSymbolAddress((void**)&p_cnt,  g_cnt);

    // ---- encoder ----
    conv_k4s2<1, 64, 256, true><<<dim3(16, 8, 32), 256>>>(x, enc_c1_w, enc_c1_b, p_big);
    conv_k4s2<64, 128, 128, true><<<dim3(4, 16, 32), 256>>>(p_big, enc_c2_w, enc_c2_b, p_x);
    // c3 stores s = relu(out); res-block state is kept pre-relu'd throughout
    conv3x3_k<128, 128, true, true><<<dim3(4, 16, 32), 256>>>(p_x, enc_c3_w, enc_c3_b, p_y);
    for (int it = 0; it < 2; it++) {
        conv3x3_k<128, 64, true, false><<<dim3(4, 8, 32), 256>>>(p_y, enc_r1_w, nullptr, p_h);
        res_add_k<<<dim3(4, 16, 32), 256>>>(p_y, p_h, enc_r2_w);
    }
    vqc_k<<<dim3(4, 8, 32), 256>>>(p_y, vqc_w, vqc_b, p_z);

    // ---- VQ ----
    init_k<<<1, 64>>>(p_cnt);
    vq_k<<<2048, 64>>>(p_z, emb, p_idx, p_ssep, p_cnt);
    // scatter writes qn into d_out (8B-aligned only) AND an aligned copy into g_z
    scatter_k<<<32768, 256>>>(p_idx, emb, out + OFF_QN, p_z);
    finalize_k<<<1, 128>>>(p_ssep, p_cnt, out, out + OFF_PERP);

    // ---- decoder ----
    wtrans_k<<<288, 256>>>(dec_c1_w, p_w1t);
    conv3x3_k<64, 128, true, true><<<dim3(4, 16, 32), 256>>>(p_z, p_w1t, dec_c1_b, p_y);
    for (int it = 0; it < 2; it++) {
        conv3x3_k<128, 64, true, false><<<dim3(4, 8, 32), 256>>>(p_y, dec_r1_w, nullptr, p_h);
        res_add_k<<<dim3(4, 16, 32), 256>>>(p_y, p_h, dec_r2_w);
    }
    deconv_c2_k<<<dim3(8, 16, 32), 256>>>(p_y, dec_c2_w, dec_c2_b, p_big);
    deconv_c3_k<<<dim3(32, 1, 32), 256>>>(p_big, dec_c3_w, dec_c3_b, out + OFF_XRE);
}